// round 10
// baseline (speedup 1.0000x reference)
#include <cuda_runtime.h>
#include <cuda_bf16.h>

#define D 8192
#define BATCH 4096
#define ROWS_PER_BLOCK 16

// Intermediate z: FWHT bits 7..12 applied (strides 128..4096), s1[0] folded.
__device__ float d_z[D];

// ---------------------------------------------------------------------------
// stageA: softplus + s1[0] + FWHT high-bit stages (element = g*128 + low,
// g = bits 7..12). 16 blocks x 256 threads; block b owns lows [b*8, b*8+8)
// for ALL 64 g — every gmem access covers full 32B sectors (8 contiguous
// floats). Transform over g via shfl after a padded smem transpose
// (stride 9: odd => conflict-free on the transform-phase access).
// ---------------------------------------------------------------------------
__global__ __launch_bounds__(256, 1)
void stageA_kernel(const float* __restrict__ s1,
                   const float* __restrict__ g_mu,
                   const float* __restrict__ g_rho,
                   const float* __restrict__ eps) {
#if __CUDA_ARCH__ >= 900
    cudaTriggerProgrammaticLaunchCompletion();   // outer's prologue may start
#endif
    __shared__ float sm[64 * 9];                 // [g][low8], row stride 9
    const int t  = threadIdx.x;
    const int b  = blockIdx.x;
    const int gi = t >> 3;                       // 0..31
    const int l  = t & 7;                        // low within block's 8
    const int e0 = gi * 128 + b * 8 + l;         // g = gi
    const int e1 = e0 + 32 * 128;                // g = gi + 32

    const float s10 = __ldg(s1);
    {   // sector-efficient loads (8 contiguous lows per 32B sector)
        float v0 = __ldg(g_rho + e0), v1 = __ldg(g_rho + e1);
        float m0 = __ldg(g_mu  + e0), m1 = __ldg(g_mu  + e1);
        float p0 = __ldg(eps   + e0), p1 = __ldg(eps   + e1);
        float sp0 = fmaxf(v0, 0.0f) + __logf(1.0f + __expf(-fabsf(v0)));
        float sp1 = fmaxf(v1, 0.0f) + __logf(1.0f + __expf(-fabsf(v1)));
        sm[gi * 9 + l]        = s10 * fmaf(sp0, p0, m0);
        sm[(gi + 32) * 9 + l] = s10 * fmaf(sp1, p1, m1);
    }
    __syncthreads();

    // transform phase: lane = g bits 0..4 (shfl), wi = low
    const int lane = t & 31;
    const int wi   = t >> 5;                     // 0..7
    float r0 = sm[lane * 9 + wi];                // conflict-free (9 odd)
    float r1 = sm[(lane + 32) * 9 + wi];

    #pragma unroll
    for (int m = 1; m <= 16; m <<= 1) {          // g bits 0..4
        const float sgn = (lane & m) ? -1.0f : 1.0f;
        float o0 = __shfl_xor_sync(0xffffffffu, r0, m);
        float o1 = __shfl_xor_sync(0xffffffffu, r1, m);
        r0 = fmaf(sgn, r0, o0);
        r1 = fmaf(sgn, r1, o1);
    }
    float a = r0 + r1;                           // g bit 5
    float c = r0 - r1;
    __syncthreads();                             // all reads done before rewrite
    sm[lane * 9 + wi]        = a;
    sm[(lane + 32) * 9 + wi] = c;
    __syncthreads();

    // sector-efficient stores (same mapping as the load phase)
    d_z[e0] = sm[gi * 9 + l];
    d_z[e1] = sm[(gi + 32) * 9 + l];
}

// ---------------------------------------------------------------------------
// outer (R3's measured-best body, 21.8us): finish low-bit FWHT stages
// (strides 1..64, confined to 128-groups), apply s2, stream the rank-1
// outer product. grid (8, 256), 256 threads, 16 rows/block, __stcs stores.
// PDL: x and s2 preloaded BEFORE the grid dependency sync.
// ---------------------------------------------------------------------------
__global__ __launch_bounds__(256)
void outer_kernel(const float* __restrict__ x,
                  const float* __restrict__ s2,
                  float* __restrict__ out) {
    __shared__ float sw[1024];
    const int tid  = threadIdx.x;
    const int lane = tid & 31;
    const int r    = tid >> 5;                    // warp = 128-group in chunk
    const int jb   = blockIdx.x * 1024;
    const int base = jb + r * 128 + lane;
    const int b0   = blockIdx.y * ROWS_PER_BLOCK;

    // ---- prologue independent of kernel 1 ----
    float xs[ROWS_PER_BLOCK];
    #pragma unroll
    for (int q = 0; q < ROWS_PER_BLOCK; q++)
        xs[q] = __ldg(x + b0 + q);

    float s2v[4];
    #pragma unroll
    for (int k = 0; k < 4; k++)
        s2v[k] = __ldg(s2 + base + k * 32);

#if __CUDA_ARCH__ >= 900
    cudaGridDependencySynchronize();              // wait for d_z
#endif

    // ---- load z chunk (lane = bits 0..4, k = bits 5..6) ----
    float rr[4];
    #pragma unroll
    for (int k = 0; k < 4; k++)
        rr[k] = d_z[base + k * 32];

    #pragma unroll
    for (int m = 1; m <= 16; m <<= 1) {           // strides 1..16
        const float sgn = (lane & m) ? -1.0f : 1.0f;
        #pragma unroll
        for (int k = 0; k < 4; k++) {
            float o = __shfl_xor_sync(0xffffffffu, rr[k], m);
            rr[k] = fmaf(sgn, rr[k], o);
        }
    }
    { // stride 32 (k bit 0)
        float a0 = rr[0], c0 = rr[1], a1 = rr[2], c1 = rr[3];
        rr[0] = a0 + c0; rr[1] = a0 - c0;
        rr[2] = a1 + c1; rr[3] = a1 - c1;
    }
    { // stride 64 (k bit 1)
        float a0 = rr[0], c0 = rr[2], a1 = rr[1], c1 = rr[3];
        rr[0] = a0 + c0; rr[2] = a0 - c0;
        rr[1] = a1 + c1; rr[3] = a1 - c1;
    }

    // apply s2; transpose through smem so each thread owns 4 contiguous cols
    #pragma unroll
    for (int k = 0; k < 4; k++)
        sw[r * 128 + k * 32 + lane] = s2v[k] * rr[k];
    __syncthreads();

    const float4 w4 = *(const float4*)&sw[tid * 4];
    const int jbase = jb + tid * 4;

    #pragma unroll
    for (int q = 0; q < ROWS_PER_BLOCK; q++) {
        float xv = xs[q];
        float4 o = make_float4(xv * w4.x, xv * w4.y, xv * w4.z, xv * w4.w);
        // 134 MB output, never re-read -> streaming (evict-first) store
        __stcs((float4*)(out + (size_t)(b0 + q) * D + jbase), o);
    }
}

extern "C" void kernel_launch(void* const* d_in, const int* in_sizes, int n_in,
                              void* d_out, int out_size) {
    const float* x     = (const float*)d_in[0];  // (4096, 1)
    const float* s1    = (const float*)d_in[1];  // (8192,)
    const float* s2    = (const float*)d_in[2];  // (8192,)
    const float* g_mu  = (const float*)d_in[3];  // (8192,)
    const float* g_rho = (const float*)d_in[4];  // (8192,)
    const float* eps   = (const float*)d_in[5];  // (8192,)
    float* out = (float*)d_out;                  // (4096, 8192) f32

    stageA_kernel<<<16, 256>>>(s1, g_mu, g_rho, eps);

    cudaLaunchConfig_t cfg = {};
    cfg.gridDim  = dim3(D / 1024, BATCH / ROWS_PER_BLOCK, 1);  // (8, 256)
    cfg.blockDim = dim3(256, 1, 1);
    cfg.stream   = 0;
    cudaLaunchAttribute attr;
    attr.id = cudaLaunchAttributeProgrammaticStreamSerialization;
    attr.val.programmaticStreamSerializationAllowed = 1;
    cfg.attrs    = &attr;
    cfg.numAttrs = 1;
    cudaLaunchKernelEx(&cfg, outer_kernel, x, s2, out);
}